// round 1
// baseline (speedup 1.0000x reference)
#include <cuda_runtime.h>
#include <cuda_bf16.h>
#include <math.h>

// Problem constants
#define BATCH   2
#define SEQ     2048
#define HID     3072
#define NH      32
#define NKV     8
#define HD      96
#define OPSZ    4608          // NH*HD + 2*NKV*HD
#define MROWS   4096          // BATCH*SEQ
#define QK_SCALE 0.10206207261596577f  // 1/sqrt(96)

// ---------------- scratch (device globals, no allocation) ----------------
__device__ float g_qkv [(size_t)MROWS * OPSZ];          // 75.5 MB
__device__ float g_q   [(size_t)BATCH * NH  * SEQ * HD]; // 50 MB  (roped+scaled)
__device__ float g_k   [(size_t)BATCH * NKV * SEQ * HD]; // 12.6 MB (roped)
__device__ float g_v   [(size_t)BATCH * NKV * SEQ * HD]; // 12.6 MB
__device__ float g_att [(size_t)MROWS * HID];            // 50 MB

// ============================ SGEMM ============================
// C[M,N] = A[M,K] @ B[K,N], row-major fp32. BM=BN=128, BK=16, 256 thr, 8x8/thr.
#define BM 128
#define BN 128
#define BK 16

__global__ __launch_bounds__(256) void sgemm_kernel(
    const float* __restrict__ A, const float* __restrict__ B,
    float* __restrict__ C, int M, int N, int K)
{
    __shared__ float As[BK][BM];   // transposed A tile
    __shared__ float Bs[BK][BN];

    const int tid = threadIdx.x;
    const int tx = tid & 15;       // 0..15 -> col groups
    const int ty = tid >> 4;       // 0..15 -> row groups
    const int bm = blockIdx.y * BM;
    const int bn = blockIdx.x * BN;

    const float* Ab = A + (size_t)bm * K;
    const float* Bb = B + bn;

    float acc[8][8];
    #pragma unroll
    for (int i = 0; i < 8; i++)
        #pragma unroll
        for (int j = 0; j < 8; j++) acc[i][j] = 0.f;

    for (int k0 = 0; k0 < K; k0 += BK) {
        // load A tile: 128x16 = 512 float4
        #pragma unroll
        for (int i = 0; i < 2; i++) {
            int f   = tid * 2 + i;          // 0..511
            int row = f >> 2;
            int cg  = (f & 3) * 4;
            float4 v = *(const float4*)(Ab + (size_t)row * K + k0 + cg);
            As[cg + 0][row] = v.x;
            As[cg + 1][row] = v.y;
            As[cg + 2][row] = v.z;
            As[cg + 3][row] = v.w;
        }
        // load B tile: 16x128 = 512 float4
        #pragma unroll
        for (int i = 0; i < 2; i++) {
            int f   = tid * 2 + i;
            int row = f >> 5;               // 0..15
            int cg  = (f & 31) * 4;         // 0..124
            *(float4*)&Bs[row][cg] =
                *(const float4*)(Bb + (size_t)(k0 + row) * N + cg);
        }
        __syncthreads();

        #pragma unroll
        for (int k = 0; k < BK; k++) {
            float ar[8], br[8];
            *(float4*)&ar[0] = *(float4*)&As[k][ty * 8];
            *(float4*)&ar[4] = *(float4*)&As[k][ty * 8 + 4];
            *(float4*)&br[0] = *(float4*)&Bs[k][tx * 8];
            *(float4*)&br[4] = *(float4*)&Bs[k][tx * 8 + 4];
            #pragma unroll
            for (int i = 0; i < 8; i++)
                #pragma unroll
                for (int j = 0; j < 8; j++)
                    acc[i][j] += ar[i] * br[j];
        }
        __syncthreads();
    }

    #pragma unroll
    for (int i = 0; i < 8; i++) {
        float* Crow = C + (size_t)(bm + ty * 8 + i) * N + bn + tx * 8;
        *(float4*)(Crow)     = make_float4(acc[i][0], acc[i][1], acc[i][2], acc[i][3]);
        *(float4*)(Crow + 4) = make_float4(acc[i][4], acc[i][5], acc[i][6], acc[i][7]);
    }
}

// ============================ RoPE + split ============================
// One block per (b,s) row of qkv. Computes cos/sin once per row.
__global__ __launch_bounds__(256) void rope_split_kernel(
    const float* __restrict__ qkv,
    float* __restrict__ Qb, float* __restrict__ Kb, float* __restrict__ Vb)
{
    const int m = blockIdx.x;          // 0..4095
    const int b = m >> 11;
    const int s = m & 2047;
    const int tid = threadIdx.x;

    __shared__ float cosr[48], sinr[48];
    if (tid < 48) {
        // mimic reference fp32 math: inv_freq = 10000^(-(2j)/96)
        float invf = powf(10000.f, -((float)(2 * tid)) / 96.f);
        float ang  = (float)s * invf;
        cosr[tid] = cosf(ang);
        sinr[tid] = sinf(ang);
    }
    __syncthreads();

    const float* row = qkv + (size_t)m * OPSZ;

    // Q heads (32) + K heads (8), each 48 rotation pairs
    for (int idx = tid; idx < (NH + NKV) * 48; idx += 256) {
        int hh = idx / 48;
        int j  = idx % 48;
        float c  = cosr[j];
        float sn = sinr[j];
        if (hh < NH) {
            float x1 = row[hh * HD + j];
            float x2 = row[hh * HD + j + 48];
            size_t base = ((size_t)(b * NH + hh)) * SEQ * HD + (size_t)s * HD;
            Qb[base + j]      = (x1 * c - x2 * sn) * QK_SCALE;
            Qb[base + j + 48] = (x2 * c + x1 * sn) * QK_SCALE;
        } else {
            int kh = hh - NH;
            float x1 = row[NH * HD + kh * HD + j];
            float x2 = row[NH * HD + kh * HD + j + 48];
            size_t base = ((size_t)(b * NKV + kh)) * SEQ * HD + (size_t)s * HD;
            Kb[base + j]      = x1 * c - x2 * sn;
            Kb[base + j + 48] = x2 * c + x1 * sn;
        }
    }
    // V copy
    for (int idx = tid; idx < NKV * HD; idx += 256) {
        int kh = idx / HD, d = idx % HD;
        Vb[((size_t)(b * NKV + kh)) * SEQ * HD + (size_t)s * HD + d] =
            row[NH * HD + NKV * HD + idx];
    }
}

// ============================ Attention ============================
// CTA = (q-tile of 64 rows, b*NH+h). Flash-style online softmax, fp32.
// smem: q[64][100], k[64][100], vT[96][68], p[64][68], stats.
#define AT_BQ   64
#define AT_BK   64
#define PQK     100
#define PS      68
#define SMEM_FLOATS (64*PQK + 64*PQK + 96*PS + 64*PS + 192)
#define ATTN_SMEM_BYTES (SMEM_FLOATS * 4)

__global__ __launch_bounds__(256) void attn_kernel(
    const float* __restrict__ Q, const float* __restrict__ K,
    const float* __restrict__ V, float* __restrict__ O)
{
    extern __shared__ float sm[];
    float* q_s  = sm;                       // [64][100]
    float* k_s  = q_s + 64 * PQK;           // [64][100]
    float* v_s  = k_s + 64 * PQK;           // [96][68] transposed: v_s[d][j]
    float* p_s  = v_s + 96 * PS;            // [64][68]
    float* m_s  = p_s + 64 * PS;            // [64]
    float* l_s  = m_s + 64;                 // [64]
    float* al_s = l_s + 64;                 // [64]

    const int tid = threadIdx.x;
    const int tx = tid & 15;
    const int ty = tid >> 4;
    const int tileq = blockIdx.x;           // 0..31
    const int bh = blockIdx.y;              // 0..63
    const int b  = bh >> 5;
    const int h  = bh & 31;
    const int kvh = h >> 2;                 // N_REP = 4
    const int q0 = tileq * AT_BQ;

    const float* Qb = Q + (size_t)bh * SEQ * HD;
    const float* Kb = K + (size_t)(b * NKV + kvh) * SEQ * HD;
    const float* Vb = V + (size_t)(b * NKV + kvh) * SEQ * HD;

    // load Q tile (already scaled by 1/sqrt(d) in rope kernel)
    for (int f = tid; f < 64 * 24; f += 256) {       // 1536 float4
        int row = f / 24;
        int cg  = (f % 24) * 4;
        *(float4*)&q_s[row * PQK + cg] =
            *(const float4*)(Qb + (size_t)(q0 + row) * HD + cg);
    }
    if (tid < 64) { m_s[tid] = -1e30f; l_s[tid] = 0.f; }

    float acc[4][6];
    #pragma unroll
    for (int i = 0; i < 4; i++)
        #pragma unroll
        for (int c = 0; c < 6; c++) acc[i][c] = 0.f;

    const int ntiles = tileq + 1;            // causal
    for (int t = 0; t < ntiles; t++) {
        const int k0 = t * AT_BK;
        __syncthreads();   // protect k_s/v_s/p_s from previous iteration readers

        // load K tile
        for (int f = tid; f < 64 * 24; f += 256) {
            int row = f / 24;
            int cg  = (f % 24) * 4;
            *(float4*)&k_s[row * PQK + cg] =
                *(const float4*)(Kb + (size_t)(k0 + row) * HD + cg);
        }
        // load V tile transposed: v_s[d][j]
        for (int e = tid; e < AT_BK * HD; e += 256) {
            int j = e / HD, d = e % HD;
            v_s[d * PS + j] = Vb[(size_t)(k0 + j) * HD + d];
        }
        __syncthreads();

        // scores: S = Q K^T, 4x4 per thread
        float s4[4][4];
        #pragma unroll
        for (int i = 0; i < 4; i++)
            #pragma unroll
            for (int j = 0; j < 4; j++) s4[i][j] = 0.f;

        #pragma unroll 4
        for (int d = 0; d < HD; d += 4) {
            float4 qa[4], kb4[4];
            #pragma unroll
            for (int i = 0; i < 4; i++)
                qa[i] = *(float4*)&q_s[(ty * 4 + i) * PQK + d];
            #pragma unroll
            for (int j = 0; j < 4; j++)
                kb4[j] = *(float4*)&k_s[(tx * 4 + j) * PQK + d];
            #pragma unroll
            for (int i = 0; i < 4; i++)
                #pragma unroll
                for (int j = 0; j < 4; j++) {
                    s4[i][j] += qa[i].x * kb4[j].x + qa[i].y * kb4[j].y
                              + qa[i].z * kb4[j].z + qa[i].w * kb4[j].w;
                }
        }
        const bool diag = (t == tileq);
        #pragma unroll
        for (int i = 0; i < 4; i++)
            #pragma unroll
            for (int j = 0; j < 4; j++) {
                int qi = q0 + ty * 4 + i;
                int kj = k0 + tx * 4 + j;
                float v = s4[i][j];
                if (diag && kj > qi) v = -1e30f;
                p_s[(ty * 4 + i) * PS + tx * 4 + j] = v;
            }
        __syncthreads();

        // online-softmax row update (64 threads, one per row)
        if (tid < 64) {
            const int r = tid;
            float mold = m_s[r];
            float mt = mold;
            #pragma unroll 8
            for (int j = 0; j < AT_BK; j++) mt = fmaxf(mt, p_s[r * PS + j]);
            float alpha = __expf(mold - mt);
            float sum = 0.f;
            #pragma unroll 8
            for (int j = 0; j < AT_BK; j++) {
                float e = __expf(p_s[r * PS + j] - mt);
                p_s[r * PS + j] = e;
                sum += e;
            }
            m_s[r]  = mt;
            l_s[r]  = l_s[r] * alpha + sum;
            al_s[r] = alpha;
        }
        __syncthreads();

        // rescale accumulators, then O += P V  (4 rows x 6 cols per thread)
        #pragma unroll
        for (int i = 0; i < 4; i++) {
            float a = al_s[ty * 4 + i];
            #pragma unroll
            for (int c = 0; c < 6; c++) acc[i][c] *= a;
        }
        #pragma unroll 4
        for (int j4 = 0; j4 < AT_BK; j4 += 4) {
            float4 p4[4], v4[6];
            #pragma unroll
            for (int i = 0; i < 4; i++)
                p4[i] = *(float4*)&p_s[(ty * 4 + i) * PS + j4];
            #pragma unroll
            for (int c = 0; c < 6; c++)
                v4[c] = *(float4*)&v_s[(tx * 6 + c) * PS + j4];
            #pragma unroll
            for (int i = 0; i < 4; i++)
                #pragma unroll
                for (int c = 0; c < 6; c++) {
                    acc[i][c] += p4[i].x * v4[c].x + p4[i].y * v4[c].y
                               + p4[i].z * v4[c].z + p4[i].w * v4[c].w;
                }
        }
    }

    // write: O is [b*SEQ + s][HID], column h*HD + col
    #pragma unroll
    for (int i = 0; i < 4; i++) {
        int r = ty * 4 + i;
        float inv = 1.f / l_s[r];
        size_t base = ((size_t)(b * SEQ + q0 + r)) * HID + h * HD + tx * 6;
        #pragma unroll
        for (int c = 0; c < 6; c++)
            O[base + c] = acc[i][c] * inv;
    }
}

// ============================ launch ============================
extern "C" void kernel_launch(void* const* d_in, const int* in_sizes, int n_in,
                              void* d_out, int out_size)
{
    const float* hs   = (const float*)d_in[0];   // hidden_states
    // d_in[1] = position_ids (arange, unused)
    // d_in[2] = attention_mask (causal, unused)
    const float* Wqkv = (const float*)d_in[3];
    const float* Wo   = (const float*)d_in[4];
    float* out = (float*)d_out;

    float *qkv, *Qb, *Kb, *Vb, *att;
    cudaGetSymbolAddress((void**)&qkv, g_qkv);
    cudaGetSymbolAddress((void**)&Qb,  g_q);
    cudaGetSymbolAddress((void**)&Kb,  g_k);
    cudaGetSymbolAddress((void**)&Vb,  g_v);
    cudaGetSymbolAddress((void**)&att, g_att);

    cudaFuncSetAttribute(attn_kernel,
                         cudaFuncAttributeMaxDynamicSharedMemorySize,
                         ATTN_SMEM_BYTES);

    // 1) QKV projection: [4096,3072] @ [3072,4608]
    sgemm_kernel<<<dim3(OPSZ / BN, MROWS / BM), 256>>>(hs, Wqkv, qkv,
                                                       MROWS, OPSZ, HID);
    // 2) RoPE + split into Q/K/V head-major buffers
    rope_split_kernel<<<MROWS, 256>>>(qkv, Qb, Kb, Vb);

    // 3) causal GQA flash attention
    attn_kernel<<<dim3(SEQ / AT_BQ, BATCH * NH), 256, ATTN_SMEM_BYTES>>>(
        Qb, Kb, Vb, att);

    // 4) output projection: [4096,3072] @ [3072,3072]
    sgemm_kernel<<<dim3(HID / BN, MROWS / BM), 256>>>(att, Wo, out,
                                                      MROWS, HID, HID);
}

// round 2
// speedup vs baseline: 1.6385x; 1.6385x over previous
#include <cuda_runtime.h>
#include <cuda_bf16.h>
#include <math.h>
#include <stdint.h>

// Problem constants
#define BATCH   2
#define SEQ     2048
#define HID     3072
#define NH      32
#define NKV     8
#define HD      96
#define OPSZ    4608          // NH*HD + 2*NKV*HD
#define MROWS   4096          // BATCH*SEQ
#define QK_SCALE 0.10206207261596577f  // 1/sqrt(96)

// ---------------- scratch (device globals, no allocation) ----------------
__device__ float g_qkv [(size_t)MROWS * OPSZ];
__device__ float g_q   [(size_t)BATCH * NH  * SEQ * HD];
__device__ float g_k   [(size_t)BATCH * NKV * SEQ * HD];
__device__ float g_v   [(size_t)BATCH * NKV * SEQ * HD];
__device__ float g_att [(size_t)MROWS * HID];

// ============================================================
//                TF32 tensor-core GEMM (mma.sync)
//  C[M,N] = A[M,K] @ B[K,N], row-major fp32 in/out.
//  CTA tile 128x128x32, 8 warps (4m x 2n), warp tile 32x64.
//  m16n8k8 tf32 MMA; inputs rounded with cvt.rna (unbiased).
// ============================================================
#define GBM 128
#define GBN 128
#define GBK 32
#define AS_STRIDE 36    // bank: (36*g + tg)%32 = (4g+tg)%32 -> bijective, conflict-free
#define BS_STRIDE 136   // bank: (136*tg + g)%32 = (8tg+g)%32 -> bijective, conflict-free

__device__ __forceinline__ uint32_t f2tf32(float x) {
    uint32_t r;
    asm("cvt.rna.tf32.f32 %0, %1;" : "=r"(r) : "f"(x));
    return r;
}

__device__ __forceinline__ void mma_tf32(float* c, const uint32_t* a, const uint32_t* b) {
    asm volatile(
        "mma.sync.aligned.m16n8k8.row.col.f32.tf32.tf32.f32 "
        "{%0,%1,%2,%3}, {%4,%5,%6,%7}, {%8,%9}, {%0,%1,%2,%3};\n"
        : "+f"(c[0]), "+f"(c[1]), "+f"(c[2]), "+f"(c[3])
        : "r"(a[0]), "r"(a[1]), "r"(a[2]), "r"(a[3]),
          "r"(b[0]), "r"(b[1]));
}

__global__ __launch_bounds__(256) void tf32_gemm_kernel(
    const float* __restrict__ A, const float* __restrict__ B,
    float* __restrict__ C, int M, int N, int K)
{
    __shared__ uint32_t As[GBM * AS_STRIDE];   // [m][k] row-major, k-stride 36
    __shared__ uint32_t Bs[GBK * BS_STRIDE];   // [k][n] row-major, n-stride 136

    const int tid  = threadIdx.x;
    const int lane = tid & 31;
    const int wid  = tid >> 5;
    const int g    = lane >> 2;   // group id (row within 8)
    const int tg   = lane & 3;    // thread in group
    const int wm   = (wid & 3) * 32;   // warp m offset in CTA tile
    const int wn   = (wid >> 2) * 64;  // warp n offset in CTA tile

    const int bm = blockIdx.y * GBM;
    const int bn = blockIdx.x * GBN;

    // ---- global load indexing (full tiles only; all dims divisible) ----
    // A tile: 128 x 32 -> 1024 float4, 4 per thread
    const int arow = tid >> 3;          // 0..31 step portion: rows tid/8 + 32*i
    const int acg  = (tid & 7) * 4;     // col group within 32
    // B tile: 32 x 128 -> 1024 float4, 4 per thread
    const int brow = tid >> 6;          // 0..3  : rows tid/64 + 8*i  (32 rows total)
    const int bcg  = (tid & 63) * 2;    // 64 threads cover 128 cols? -> use float2? no:
    // simpler mapping: f = tid + 256*i ; row = f>>5 ; cg = (f&31)*4

    float4 ra[4], rb[4];

    // prologue: load k0 = 0
    {
        #pragma unroll
        for (int i = 0; i < 4; i++) {
            int f = tid + 256 * i;
            int r = f >> 3;             // 0..127
            int c = (f & 7) * 4;        // 0..28
            ra[i] = *(const float4*)(A + (size_t)(bm + r) * K + c);
        }
        #pragma unroll
        for (int i = 0; i < 4; i++) {
            int f = tid + 256 * i;
            int r = f >> 5;             // 0..31
            int c = (f & 31) * 4;       // 0..124
            rb[i] = *(const float4*)(B + (size_t)r * N + bn + c);
        }
    }

    float acc[2][8][4];
    #pragma unroll
    for (int mt = 0; mt < 2; mt++)
        #pragma unroll
        for (int nt = 0; nt < 8; nt++)
            #pragma unroll
            for (int e = 0; e < 4; e++) acc[mt][nt][e] = 0.f;

    for (int k0 = 0; k0 < K; k0 += GBK) {
        // ---- store staged tile to smem (with tf32 rounding) ----
        #pragma unroll
        for (int i = 0; i < 4; i++) {
            int f = tid + 256 * i;
            int r = f >> 3;
            int c = (f & 7) * 4;
            uint32_t* p = &As[r * AS_STRIDE + c];
            p[0] = f2tf32(ra[i].x);
            p[1] = f2tf32(ra[i].y);
            p[2] = f2tf32(ra[i].z);
            p[3] = f2tf32(ra[i].w);
        }
        #pragma unroll
        for (int i = 0; i < 4; i++) {
            int f = tid + 256 * i;
            int r = f >> 5;
            int c = (f & 31) * 4;
            uint32_t* p = &Bs[r * BS_STRIDE + c];
            p[0] = f2tf32(rb[i].x);
            p[1] = f2tf32(rb[i].y);
            p[2] = f2tf32(rb[i].z);
            p[3] = f2tf32(rb[i].w);
        }
        __syncthreads();

        // ---- prefetch next tile into registers ----
        if (k0 + GBK < K) {
            int kn = k0 + GBK;
            #pragma unroll
            for (int i = 0; i < 4; i++) {
                int f = tid + 256 * i;
                int r = f >> 3;
                int c = (f & 7) * 4;
                ra[i] = *(const float4*)(A + (size_t)(bm + r) * K + kn + c);
            }
            #pragma unroll
            for (int i = 0; i < 4; i++) {
                int f = tid + 256 * i;
                int r = f >> 5;
                int c = (f & 31) * 4;
                rb[i] = *(const float4*)(B + (size_t)(kn + r) * N + bn + c);
            }
        }

        // ---- compute: 4 k-chunks of 8 ----
        #pragma unroll
        for (int kc = 0; kc < 4; kc++) {
            uint32_t afrag[2][4];
            uint32_t bfrag[8][2];
            #pragma unroll
            for (int mt = 0; mt < 2; mt++) {
                int r = wm + mt * 16 + g;
                int kk = kc * 8 + tg;
                afrag[mt][0] = As[r * AS_STRIDE + kk];
                afrag[mt][1] = As[(r + 8) * AS_STRIDE + kk];
                afrag[mt][2] = As[r * AS_STRIDE + kk + 4];
                afrag[mt][3] = As[(r + 8) * AS_STRIDE + kk + 4];
            }
            #pragma unroll
            for (int nt = 0; nt < 8; nt++) {
                int cc = wn + nt * 8 + g;
                bfrag[nt][0] = Bs[(kc * 8 + tg) * BS_STRIDE + cc];
                bfrag[nt][1] = Bs[(kc * 8 + tg + 4) * BS_STRIDE + cc];
            }
            #pragma unroll
            for (int mt = 0; mt < 2; mt++)
                #pragma unroll
                for (int nt = 0; nt < 8; nt++)
                    mma_tf32(acc[mt][nt], afrag[mt], bfrag[nt]);
        }
        __syncthreads();
    }

    // ---- epilogue: write C ----
    #pragma unroll
    for (int mt = 0; mt < 2; mt++) {
        int r0 = bm + wm + mt * 16 + g;
        #pragma unroll
        for (int nt = 0; nt < 8; nt++) {
            int c0 = bn + wn + nt * 8 + tg * 2;
            float2 lo = make_float2(acc[mt][nt][0], acc[mt][nt][1]);
            float2 hi = make_float2(acc[mt][nt][2], acc[mt][nt][3]);
            *(float2*)(C + (size_t)r0 * N + c0)       = lo;
            *(float2*)(C + (size_t)(r0 + 8) * N + c0) = hi;
        }
    }
}

// ============================ RoPE + split ============================
__global__ __launch_bounds__(256) void rope_split_kernel(
    const float* __restrict__ qkv,
    float* __restrict__ Qb, float* __restrict__ Kb, float* __restrict__ Vb)
{
    const int m = blockIdx.x;          // 0..4095
    const int b = m >> 11;
    const int s = m & 2047;
    const int tid = threadIdx.x;

    __shared__ float cosr[48], sinr[48];
    if (tid < 48) {
        float invf = powf(10000.f, -((float)(2 * tid)) / 96.f);
        float ang  = (float)s * invf;
        cosr[tid] = cosf(ang);
        sinr[tid] = sinf(ang);
    }
    __syncthreads();

    const float* row = qkv + (size_t)m * OPSZ;

    for (int idx = tid; idx < (NH + NKV) * 48; idx += 256) {
        int hh = idx / 48;
        int j  = idx % 48;
        float c  = cosr[j];
        float sn = sinr[j];
        if (hh < NH) {
            float x1 = row[hh * HD + j];
            float x2 = row[hh * HD + j + 48];
            size_t base = ((size_t)(b * NH + hh)) * SEQ * HD + (size_t)s * HD;
            Qb[base + j]      = (x1 * c - x2 * sn) * QK_SCALE;
            Qb[base + j + 48] = (x2 * c + x1 * sn) * QK_SCALE;
        } else {
            int kh = hh - NH;
            float x1 = row[NH * HD + kh * HD + j];
            float x2 = row[NH * HD + kh * HD + j + 48];
            size_t base = ((size_t)(b * NKV + kh)) * SEQ * HD + (size_t)s * HD;
            Kb[base + j]      = x1 * c - x2 * sn;
            Kb[base + j + 48] = x2 * c + x1 * sn;
        }
    }
    for (int idx = tid; idx < NKV * HD; idx += 256) {
        int kh = idx / HD, d = idx % HD;
        Vb[((size_t)(b * NKV + kh)) * SEQ * HD + (size_t)s * HD + d] =
            row[NH * HD + NKV * HD + idx];
    }
}

// ============================ Attention ============================
#define AT_BQ   64
#define AT_BK   64
#define PQK     100
#define PS      68
#define SMEM_FLOATS (64*PQK + 64*PQK + 96*PS + 64*PS + 192)
#define ATTN_SMEM_BYTES (SMEM_FLOATS * 4)

__global__ __launch_bounds__(256) void attn_kernel(
    const float* __restrict__ Q, const float* __restrict__ K,
    const float* __restrict__ V, float* __restrict__ O)
{
    extern __shared__ float sm[];
    float* q_s  = sm;                       // [64][100]
    float* k_s  = q_s + 64 * PQK;           // [64][100]
    float* v_s  = k_s + 64 * PQK;           // [96][68] transposed: v_s[d][j]
    float* p_s  = v_s + 96 * PS;            // [64][68]
    float* m_s  = p_s + 64 * PS;            // [64]
    float* l_s  = m_s + 64;                 // [64]
    float* al_s = l_s + 64;                 // [64]

    const int tid = threadIdx.x;
    const int tx = tid & 15;
    const int ty = tid >> 4;
    const int tileq = blockIdx.x;
    const int bh = blockIdx.y;
    const int b  = bh >> 5;
    const int h  = bh & 31;
    const int kvh = h >> 2;
    const int q0 = tileq * AT_BQ;

    const float* Qb = Q + (size_t)bh * SEQ * HD;
    const float* Kb = K + (size_t)(b * NKV + kvh) * SEQ * HD;
    const float* Vb = V + (size_t)(b * NKV + kvh) * SEQ * HD;

    for (int f = tid; f < 64 * 24; f += 256) {
        int row = f / 24;
        int cg  = (f % 24) * 4;
        *(float4*)&q_s[row * PQK + cg] =
            *(const float4*)(Qb + (size_t)(q0 + row) * HD + cg);
    }
    if (tid < 64) { m_s[tid] = -1e30f; l_s[tid] = 0.f; }

    float acc[4][6];
    #pragma unroll
    for (int i = 0; i < 4; i++)
        #pragma unroll
        for (int c = 0; c < 6; c++) acc[i][c] = 0.f;

    const int ntiles = tileq + 1;
    for (int t = 0; t < ntiles; t++) {
        const int k0 = t * AT_BK;
        __syncthreads();

        for (int f = tid; f < 64 * 24; f += 256) {
            int row = f / 24;
            int cg  = (f % 24) * 4;
            *(float4*)&k_s[row * PQK + cg] =
                *(const float4*)(Kb + (size_t)(k0 + row) * HD + cg);
        }
        for (int e = tid; e < AT_BK * HD; e += 256) {
            int j = e / HD, d = e % HD;
            v_s[d * PS + j] = Vb[(size_t)(k0 + j) * HD + d];
        }
        __syncthreads();

        float s4[4][4];
        #pragma unroll
        for (int i = 0; i < 4; i++)
            #pragma unroll
            for (int j = 0; j < 4; j++) s4[i][j] = 0.f;

        #pragma unroll 4
        for (int d = 0; d < HD; d += 4) {
            float4 qa[4], kb4[4];
            #pragma unroll
            for (int i = 0; i < 4; i++)
                qa[i] = *(float4*)&q_s[(ty * 4 + i) * PQK + d];
            #pragma unroll
            for (int j = 0; j < 4; j++)
                kb4[j] = *(float4*)&k_s[(tx * 4 + j) * PQK + d];
            #pragma unroll
            for (int i = 0; i < 4; i++)
                #pragma unroll
                for (int j = 0; j < 4; j++) {
                    s4[i][j] += qa[i].x * kb4[j].x + qa[i].y * kb4[j].y
                              + qa[i].z * kb4[j].z + qa[i].w * kb4[j].w;
                }
        }
        const bool diag = (t == tileq);
        #pragma unroll
        for (int i = 0; i < 4; i++)
            #pragma unroll
            for (int j = 0; j < 4; j++) {
                int qi = q0 + ty * 4 + i;
                int kj = k0 + tx * 4 + j;
                float v = s4[i][j];
                if (diag && kj > qi) v = -1e30f;
                p_s[(ty * 4 + i) * PS + tx * 4 + j] = v;
            }
        __syncthreads();

        if (tid < 64) {
            const int r = tid;
            float mold = m_s[r];
            float mt = mold;
            #pragma unroll 8
            for (int j = 0; j < AT_BK; j++) mt = fmaxf(mt, p_s[r * PS + j]);
            float alpha = __expf(mold - mt);
            float sum = 0.f;
            #pragma unroll 8
            for (int j = 0; j < AT_BK; j++) {
                float e = __expf(p_s[r * PS + j] - mt);
                p_s[r * PS + j] = e;
                sum += e;
            }
            m_s[r]  = mt;
            l_s[r]  = l_s[r] * alpha + sum;
            al_s[r] = alpha;
        }
        __syncthreads();

        #pragma unroll
        for (int i = 0; i < 4; i++) {
            float a = al_s[ty * 4 + i];
            #pragma unroll
            for (int c = 0; c < 6; c++) acc[i][c] *= a;
        }
        #pragma unroll 4
        for (int j4 = 0; j4 < AT_BK; j4 += 4) {
            float4 p4[4], v4[6];
            #pragma unroll
            for (int i = 0; i < 4; i++)
                p4[i] = *(float4*)&p_s[(ty * 4 + i) * PS + j4];
            #pragma unroll
            for (int c = 0; c < 6; c++)
                v4[c] = *(float4*)&v_s[(tx * 6 + c) * PS + j4];
            #pragma unroll
            for (int i = 0; i < 4; i++)
                #pragma unroll
                for (int c = 0; c < 6; c++) {
                    acc[i][c] += p4[i].x * v4[c].x + p4[i].y * v4[c].y
                               + p4[i].z * v4[c].z + p4[i].w * v4[c].w;
                }
        }
    }

    #pragma unroll
    for (int i = 0; i < 4; i++) {
        int r = ty * 4 + i;
        float inv = 1.f / l_s[r];
        size_t base = ((size_t)(b * SEQ + q0 + r)) * HID + h * HD + tx * 6;
        #pragma unroll
        for (int c = 0; c < 6; c++)
            O[base + c] = acc[i][c] * inv;
    }
}

// ============================ launch ============================
extern "C" void kernel_launch(void* const* d_in, const int* in_sizes, int n_in,
                              void* d_out, int out_size)
{
    const float* hs   = (const float*)d_in[0];   // hidden_states
    // d_in[1] = position_ids (arange, unused)
    // d_in[2] = attention_mask (causal, unused)
    const float* Wqkv = (const float*)d_in[3];
    const float* Wo   = (const float*)d_in[4];
    float* out = (float*)d_out;

    float *qkv, *Qb, *Kb, *Vb, *att;
    cudaGetSymbolAddress((void**)&qkv, g_qkv);
    cudaGetSymbolAddress((void**)&Qb,  g_q);
    cudaGetSymbolAddress((void**)&Kb,  g_k);
    cudaGetSymbolAddress((void**)&Vb,  g_v);
    cudaGetSymbolAddress((void**)&att, g_att);

    cudaFuncSetAttribute(attn_kernel,
                         cudaFuncAttributeMaxDynamicSharedMemorySize,
                         ATTN_SMEM_BYTES);

    // 1) QKV projection: [4096,3072] @ [3072,4608]  (tf32 tensor cores)
    tf32_gemm_kernel<<<dim3(OPSZ / GBN, MROWS / GBM), 256>>>(hs, Wqkv, qkv,
                                                             MROWS, OPSZ, HID);
    // 2) RoPE + split into Q/K/V head-major buffers
    rope_split_kernel<<<MROWS, 256>>>(qkv, Qb, Kb, Vb);

    // 3) causal GQA flash attention (fp32, unchanged this round)
    attn_kernel<<<dim3(SEQ / AT_BQ, BATCH * NH), 256, ATTN_SMEM_BYTES>>>(
        Qb, Kb, Vb, att);

    // 4) output projection: [4096,3072] @ [3072,3072]  (tf32 tensor cores)
    tf32_gemm_kernel<<<dim3(HID / GBN, MROWS / GBM), 256>>>(att, Wo, out,
                                                            MROWS, HID, HID);
}

// round 3
// speedup vs baseline: 3.2906x; 2.0083x over previous
#include <cuda_runtime.h>
#include <cuda_bf16.h>
#include <math.h>
#include <stdint.h>

// Problem constants
#define BATCH   2
#define SEQ     2048
#define HID     3072
#define NH      32
#define NKV     8
#define HD      96
#define OPSZ    4608          // NH*HD + 2*NKV*HD
#define MROWS   4096          // BATCH*SEQ
#define QK_SCALE 0.10206207261596577f  // 1/sqrt(96)

// ---------------- scratch (device globals, no allocation) ----------------
__device__ float g_qkv [(size_t)MROWS * OPSZ];
__device__ float g_q   [(size_t)BATCH * NH  * SEQ * HD];
__device__ float g_k   [(size_t)BATCH * NKV * SEQ * HD];
__device__ float g_v   [(size_t)BATCH * NKV * SEQ * HD];
__device__ float g_att [(size_t)MROWS * HID];

// ============================================================
//          TF32 MMA helpers (m16n8k8, fp32 accumulate)
// ============================================================
__device__ __forceinline__ uint32_t f2tf32(float x) {
    uint32_t r;
    asm("cvt.rna.tf32.f32 %0, %1;" : "=r"(r) : "f"(x));
    return r;
}

__device__ __forceinline__ void mma_tf32(float* c, const uint32_t* a, const uint32_t* b) {
    asm volatile(
        "mma.sync.aligned.m16n8k8.row.col.f32.tf32.tf32.f32 "
        "{%0,%1,%2,%3}, {%4,%5,%6,%7}, {%8,%9}, {%0,%1,%2,%3};\n"
        : "+f"(c[0]), "+f"(c[1]), "+f"(c[2]), "+f"(c[3])
        : "r"(a[0]), "r"(a[1]), "r"(a[2]), "r"(a[3]),
          "r"(b[0]), "r"(b[1]));
}

// ============================================================
//                TF32 tensor-core GEMM
//  C[M,N] = A[M,K] @ B[K,N], row-major fp32 in/out.
//  CTA tile 128x128x32, 8 warps (4m x 2n), warp tile 32x64.
// ============================================================
#define GBM 128
#define GBN 128
#define GBK 32
#define AS_STRIDE 36
#define BS_STRIDE 136

__global__ __launch_bounds__(256) void tf32_gemm_kernel(
    const float* __restrict__ A, const float* __restrict__ B,
    float* __restrict__ C, int M, int N, int K)
{
    __shared__ uint32_t As[GBM * AS_STRIDE];
    __shared__ uint32_t Bs[GBK * BS_STRIDE];

    const int tid  = threadIdx.x;
    const int lane = tid & 31;
    const int wid  = tid >> 5;
    const int g    = lane >> 2;
    const int tg   = lane & 3;
    const int wm   = (wid & 3) * 32;
    const int wn   = (wid >> 2) * 64;

    const int bm = blockIdx.y * GBM;
    const int bn = blockIdx.x * GBN;

    float4 ra[4], rb[4];

    {
        #pragma unroll
        for (int i = 0; i < 4; i++) {
            int f = tid + 256 * i;
            int r = f >> 3;
            int c = (f & 7) * 4;
            ra[i] = *(const float4*)(A + (size_t)(bm + r) * K + c);
        }
        #pragma unroll
        for (int i = 0; i < 4; i++) {
            int f = tid + 256 * i;
            int r = f >> 5;
            int c = (f & 31) * 4;
            rb[i] = *(const float4*)(B + (size_t)r * N + bn + c);
        }
    }

    float acc[2][8][4];
    #pragma unroll
    for (int mt = 0; mt < 2; mt++)
        #pragma unroll
        for (int nt = 0; nt < 8; nt++)
            #pragma unroll
            for (int e = 0; e < 4; e++) acc[mt][nt][e] = 0.f;

    for (int k0 = 0; k0 < K; k0 += GBK) {
        #pragma unroll
        for (int i = 0; i < 4; i++) {
            int f = tid + 256 * i;
            int r = f >> 3;
            int c = (f & 7) * 4;
            uint32_t* p = &As[r * AS_STRIDE + c];
            p[0] = f2tf32(ra[i].x);
            p[1] = f2tf32(ra[i].y);
            p[2] = f2tf32(ra[i].z);
            p[3] = f2tf32(ra[i].w);
        }
        #pragma unroll
        for (int i = 0; i < 4; i++) {
            int f = tid + 256 * i;
            int r = f >> 5;
            int c = (f & 31) * 4;
            uint32_t* p = &Bs[r * BS_STRIDE + c];
            p[0] = f2tf32(rb[i].x);
            p[1] = f2tf32(rb[i].y);
            p[2] = f2tf32(rb[i].z);
            p[3] = f2tf32(rb[i].w);
        }
        __syncthreads();

        if (k0 + GBK < K) {
            int kn = k0 + GBK;
            #pragma unroll
            for (int i = 0; i < 4; i++) {
                int f = tid + 256 * i;
                int r = f >> 3;
                int c = (f & 7) * 4;
                ra[i] = *(const float4*)(A + (size_t)(bm + r) * K + kn + c);
            }
            #pragma unroll
            for (int i = 0; i < 4; i++) {
                int f = tid + 256 * i;
                int r = f >> 5;
                int c = (f & 31) * 4;
                rb[i] = *(const float4*)(B + (size_t)(kn + r) * N + bn + c);
            }
        }

        #pragma unroll
        for (int kc = 0; kc < 4; kc++) {
            uint32_t afrag[2][4];
            uint32_t bfrag[8][2];
            #pragma unroll
            for (int mt = 0; mt < 2; mt++) {
                int r = wm + mt * 16 + g;
                int kk = kc * 8 + tg;
                afrag[mt][0] = As[r * AS_STRIDE + kk];
                afrag[mt][1] = As[(r + 8) * AS_STRIDE + kk];
                afrag[mt][2] = As[r * AS_STRIDE + kk + 4];
                afrag[mt][3] = As[(r + 8) * AS_STRIDE + kk + 4];
            }
            #pragma unroll
            for (int nt = 0; nt < 8; nt++) {
                int cc = wn + nt * 8 + g;
                bfrag[nt][0] = Bs[(kc * 8 + tg) * BS_STRIDE + cc];
                bfrag[nt][1] = Bs[(kc * 8 + tg + 4) * BS_STRIDE + cc];
            }
            #pragma unroll
            for (int mt = 0; mt < 2; mt++)
                #pragma unroll
                for (int nt = 0; nt < 8; nt++)
                    mma_tf32(acc[mt][nt], afrag[mt], bfrag[nt]);
        }
        __syncthreads();
    }

    #pragma unroll
    for (int mt = 0; mt < 2; mt++) {
        int r0 = bm + wm + mt * 16 + g;
        #pragma unroll
        for (int nt = 0; nt < 8; nt++) {
            int c0 = bn + wn + nt * 8 + tg * 2;
            float2 lo = make_float2(acc[mt][nt][0], acc[mt][nt][1]);
            float2 hi = make_float2(acc[mt][nt][2], acc[mt][nt][3]);
            *(float2*)(C + (size_t)r0 * N + c0)       = lo;
            *(float2*)(C + (size_t)(r0 + 8) * N + c0) = hi;
        }
    }
}

// ============================ RoPE + split ============================
__global__ __launch_bounds__(256) void rope_split_kernel(
    const float* __restrict__ qkv,
    float* __restrict__ Qb, float* __restrict__ Kb, float* __restrict__ Vb)
{
    const int m = blockIdx.x;
    const int b = m >> 11;
    const int s = m & 2047;
    const int tid = threadIdx.x;

    __shared__ float cosr[48], sinr[48];
    if (tid < 48) {
        float invf = powf(10000.f, -((float)(2 * tid)) / 96.f);
        float ang  = (float)s * invf;
        cosr[tid] = cosf(ang);
        sinr[tid] = sinf(ang);
    }
    __syncthreads();

    const float* row = qkv + (size_t)m * OPSZ;

    for (int idx = tid; idx < (NH + NKV) * 48; idx += 256) {
        int hh = idx / 48;
        int j  = idx % 48;
        float c  = cosr[j];
        float sn = sinr[j];
        if (hh < NH) {
            float x1 = row[hh * HD + j];
            float x2 = row[hh * HD + j + 48];
            size_t base = ((size_t)(b * NH + hh)) * SEQ * HD + (size_t)s * HD;
            Qb[base + j]      = (x1 * c - x2 * sn) * QK_SCALE;
            Qb[base + j + 48] = (x2 * c + x1 * sn) * QK_SCALE;
        } else {
            int kh = hh - NH;
            float x1 = row[NH * HD + kh * HD + j];
            float x2 = row[NH * HD + kh * HD + j + 48];
            size_t base = ((size_t)(b * NKV + kh)) * SEQ * HD + (size_t)s * HD;
            Kb[base + j]      = x1 * c - x2 * sn;
            Kb[base + j + 48] = x2 * c + x1 * sn;
        }
    }
    for (int idx = tid; idx < NKV * HD; idx += 256) {
        int kh = idx / HD, d = idx % HD;
        Vb[((size_t)(b * NKV + kh)) * SEQ * HD + (size_t)s * HD + d] =
            row[NH * HD + NKV * HD + idx];
    }
}

// ============================================================
//          Tensor-core flash attention (tf32 MMA)
//  CTA = (64 q-rows, b*NH+h). 256 threads, 8 warps.
//  QK: warps 4m x 2n -> warp tile 16x32.  PV: 16x48.
// ============================================================
#define AT_BQ 64
#define AT_BK 64
#define QK_STRIDE 100   // % 32 == 4 -> conflict-free frag loads
#define V_STRIDE  104   // % 32 == 8 -> conflict-free k-indexed loads
#define P_STRIDE  68    // % 32 == 4

#define ATTN_SMEM_U32 (AT_BQ*QK_STRIDE + AT_BK*QK_STRIDE + AT_BK*V_STRIDE + AT_BQ*P_STRIDE + 3*AT_BQ)
#define ATTN_SMEM_BYTES (ATTN_SMEM_U32 * 4)

__global__ __launch_bounds__(256, 2) void attn_tc_kernel(
    const float* __restrict__ Q, const float* __restrict__ K,
    const float* __restrict__ V, float* __restrict__ O)
{
    extern __shared__ uint32_t smu[];
    uint32_t* q_s = smu;                          // [64][100] tf32
    uint32_t* k_s = q_s + AT_BQ * QK_STRIDE;      // [64][100] tf32
    uint32_t* v_s = k_s + AT_BK * QK_STRIDE;      // [64][104] tf32 (row j, col d)
    float*    p_s = (float*)(v_s + AT_BK * V_STRIDE); // [64][68]
    float*    m_s = p_s + AT_BQ * P_STRIDE;       // [64]
    float*    l_s = m_s + AT_BQ;
    float*    al_s = l_s + AT_BQ;

    const int tid  = threadIdx.x;
    const int lane = tid & 31;
    const int wid  = tid >> 5;
    const int g    = lane >> 2;
    const int tg   = lane & 3;
    const int wm   = (wid & 3) * 16;       // warp q-row offset
    const int wn   = (wid >> 2) * 32;      // warp kv-col offset (QK)
    const int wnp  = (wid >> 2) * 48;      // warp d-col offset (PV)

    const int tileq = blockIdx.x;          // 0..31
    const int bh = blockIdx.y;             // 0..63
    const int b  = bh >> 5;
    const int h  = bh & 31;
    const int kvh = h >> 2;
    const int q0 = tileq * AT_BQ;

    const float* Qb = Q + (size_t)bh * SEQ * HD;
    const float* Kb = K + (size_t)(b * NKV + kvh) * SEQ * HD;
    const float* Vb = V + (size_t)(b * NKV + kvh) * SEQ * HD;

    // ---- load Q tile (pre-scaled), rounded to tf32 ----
    for (int f = tid; f < AT_BQ * 24; f += 256) {
        int row = f / 24;
        int cg  = (f % 24) * 4;
        float4 v = *(const float4*)(Qb + (size_t)(q0 + row) * HD + cg);
        uint32_t* p = &q_s[row * QK_STRIDE + cg];
        p[0] = f2tf32(v.x); p[1] = f2tf32(v.y);
        p[2] = f2tf32(v.z); p[3] = f2tf32(v.w);
    }
    if (tid < AT_BQ) { m_s[tid] = -1e30f; l_s[tid] = 0.f; }

    // O accumulator fragments: 6 n-frags of m16n8
    float acc[6][4];
    #pragma unroll
    for (int nt = 0; nt < 6; nt++)
        #pragma unroll
        for (int e = 0; e < 4; e++) acc[nt][e] = 0.f;

    const int ntiles = tileq + 1;
    for (int t = 0; t < ntiles; t++) {
        const int k0 = t * AT_BK;
        __syncthreads();   // protect k_s/v_s/p_s from previous iteration readers

        // ---- load K, V tiles (tf32) ----
        for (int f = tid; f < AT_BK * 24; f += 256) {
            int row = f / 24;
            int cg  = (f % 24) * 4;
            float4 kv4 = *(const float4*)(Kb + (size_t)(k0 + row) * HD + cg);
            uint32_t* p = &k_s[row * QK_STRIDE + cg];
            p[0] = f2tf32(kv4.x); p[1] = f2tf32(kv4.y);
            p[2] = f2tf32(kv4.z); p[3] = f2tf32(kv4.w);
            float4 vv4 = *(const float4*)(Vb + (size_t)(k0 + row) * HD + cg);
            uint32_t* pv = &v_s[row * V_STRIDE + cg];
            pv[0] = f2tf32(vv4.x); pv[1] = f2tf32(vv4.y);
            pv[2] = f2tf32(vv4.z); pv[3] = f2tf32(vv4.w);
        }
        __syncthreads();

        // ---- S = Q K^T via MMA: 1 m-frag x 4 n-frags, K=96 ----
        float s4[4][4];
        #pragma unroll
        for (int nt = 0; nt < 4; nt++)
            #pragma unroll
            for (int e = 0; e < 4; e++) s4[nt][e] = 0.f;

        #pragma unroll
        for (int kc = 0; kc < 12; kc++) {
            const int kk = kc * 8 + tg;
            uint32_t a[4];
            a[0] = q_s[(wm + g) * QK_STRIDE + kk];
            a[1] = q_s[(wm + g + 8) * QK_STRIDE + kk];
            a[2] = q_s[(wm + g) * QK_STRIDE + kk + 4];
            a[3] = q_s[(wm + g + 8) * QK_STRIDE + kk + 4];
            #pragma unroll
            for (int nt = 0; nt < 4; nt++) {
                uint32_t bfr[2];
                const int j = wn + nt * 8 + g;
                bfr[0] = k_s[j * QK_STRIDE + kk];
                bfr[1] = k_s[j * QK_STRIDE + kk + 4];
                mma_tf32(s4[nt], a, bfr);
            }
        }

        // ---- mask (diag tile) + store scores ----
        const bool diag = (t == tileq);
        const int row0 = q0 + wm + g;
        #pragma unroll
        for (int nt = 0; nt < 4; nt++) {
            int col = k0 + wn + nt * 8 + 2 * tg;
            float v0 = s4[nt][0], v1 = s4[nt][1];
            float v2 = s4[nt][2], v3 = s4[nt][3];
            if (diag) {
                if (col     > row0)     v0 = -1e30f;
                if (col + 1 > row0)     v1 = -1e30f;
                if (col     > row0 + 8) v2 = -1e30f;
                if (col + 1 > row0 + 8) v3 = -1e30f;
            }
            int c = wn + nt * 8 + 2 * tg;
            *(float2*)&p_s[(wm + g) * P_STRIDE + c]     = make_float2(v0, v1);
            *(float2*)&p_s[(wm + g + 8) * P_STRIDE + c] = make_float2(v2, v3);
        }
        __syncthreads();

        // ---- online softmax: 4 threads per row, 16 cols each ----
        {
            const int r  = tid >> 2;
            const int qt = tid & 3;
            float* prow = &p_s[r * P_STRIDE + qt * 16];
            float mold = m_s[r];
            float mt = mold;
            #pragma unroll
            for (int j = 0; j < 16; j++) mt = fmaxf(mt, prow[j]);
            mt = fmaxf(mt, __shfl_xor_sync(0xffffffffu, mt, 1));
            mt = fmaxf(mt, __shfl_xor_sync(0xffffffffu, mt, 2));
            float alpha = __expf(mold - mt);
            float sum = 0.f;
            #pragma unroll
            for (int j = 0; j < 16; j++) {
                float e = __expf(prow[j] - mt);
                sum += e;
                prow[j] = __uint_as_float(f2tf32(e));  // pre-round for MMA
            }
            sum += __shfl_xor_sync(0xffffffffu, sum, 1);
            sum += __shfl_xor_sync(0xffffffffu, sum, 2);
            if (qt == 0) {
                m_s[r]  = mt;
                l_s[r]  = l_s[r] * alpha + sum;
                al_s[r] = alpha;
            }
        }
        __syncthreads();

        // ---- rescale O accumulators ----
        {
            float a0 = al_s[wm + g];
            float a1 = al_s[wm + g + 8];
            #pragma unroll
            for (int nt = 0; nt < 6; nt++) {
                acc[nt][0] *= a0; acc[nt][1] *= a0;
                acc[nt][2] *= a1; acc[nt][3] *= a1;
            }
        }

        // ---- O += P V via MMA: 1 m-frag x 6 n-frags, K=64 ----
        #pragma unroll
        for (int kc = 0; kc < 8; kc++) {
            const int kk = kc * 8 + tg;
            uint32_t a[4];
            a[0] = __float_as_uint(p_s[(wm + g) * P_STRIDE + kk]);
            a[1] = __float_as_uint(p_s[(wm + g + 8) * P_STRIDE + kk]);
            a[2] = __float_as_uint(p_s[(wm + g) * P_STRIDE + kk + 4]);
            a[3] = __float_as_uint(p_s[(wm + g + 8) * P_STRIDE + kk + 4]);
            #pragma unroll
            for (int nt = 0; nt < 6; nt++) {
                uint32_t bfr[2];
                const int d = wnp + nt * 8 + g;
                bfr[0] = v_s[kk * V_STRIDE + d];
                bfr[1] = v_s[(kk + 4) * V_STRIDE + d];
                mma_tf32(acc[nt], a, bfr);
            }
        }
    }

    // ---- epilogue: normalize and write O ----
    {
        const int r0 = wm + g;
        const float inv0 = 1.f / l_s[r0];
        const float inv1 = 1.f / l_s[r0 + 8];
        size_t base0 = ((size_t)(b * SEQ + q0 + r0)) * HID + h * HD;
        size_t base1 = base0 + 8 * HID;
        #pragma unroll
        for (int nt = 0; nt < 6; nt++) {
            int c = wnp + nt * 8 + 2 * tg;
            *(float2*)(O + base0 + c) = make_float2(acc[nt][0] * inv0, acc[nt][1] * inv0);
            *(float2*)(O + base1 + c) = make_float2(acc[nt][2] * inv1, acc[nt][3] * inv1);
        }
    }
}

// ============================ launch ============================
extern "C" void kernel_launch(void* const* d_in, const int* in_sizes, int n_in,
                              void* d_out, int out_size)
{
    const float* hs   = (const float*)d_in[0];   // hidden_states
    // d_in[1] = position_ids (arange, unused)
    // d_in[2] = attention_mask (causal, unused)
    const float* Wqkv = (const float*)d_in[3];
    const float* Wo   = (const float*)d_in[4];
    float* out = (float*)d_out;

    float *qkv, *Qb, *Kb, *Vb, *att;
    cudaGetSymbolAddress((void**)&qkv, g_qkv);
    cudaGetSymbolAddress((void**)&Qb,  g_q);
    cudaGetSymbolAddress((void**)&Kb,  g_k);
    cudaGetSymbolAddress((void**)&Vb,  g_v);
    cudaGetSymbolAddress((void**)&att, g_att);

    cudaFuncSetAttribute(attn_tc_kernel,
                         cudaFuncAttributeMaxDynamicSharedMemorySize,
                         ATTN_SMEM_BYTES);

    // 1) QKV projection (tf32 tensor cores)
    tf32_gemm_kernel<<<dim3(OPSZ / GBN, MROWS / GBM), 256>>>(hs, Wqkv, qkv,
                                                             MROWS, OPSZ, HID);
    // 2) RoPE + split
    rope_split_kernel<<<MROWS, 256>>>(qkv, Qb, Kb, Vb);

    // 3) causal GQA flash attention (tf32 tensor cores)
    attn_tc_kernel<<<dim3(SEQ / AT_BQ, BATCH * NH), 256, ATTN_SMEM_BYTES>>>(
        Qb, Kb, Vb, att);

    // 4) output projection (tf32 tensor cores)
    tf32_gemm_kernel<<<dim3(HID / GBN, MROWS / GBM), 256>>>(att, Wo, out,
                                                            MROWS, HID, HID);
}

// round 4
// speedup vs baseline: 3.6783x; 1.1178x over previous
#include <cuda_runtime.h>
#include <cuda_bf16.h>
#include <math.h>
#include <stdint.h>

// Problem constants
#define BATCH   2
#define SEQ     2048
#define HID     3072
#define NH      32
#define NKV     8
#define HD      96
#define OPSZ    4608          // NH*HD + 2*NKV*HD
#define MROWS   4096          // BATCH*SEQ
#define QK_SCALE 0.10206207261596577f  // 1/sqrt(96)

// ---------------- scratch (device globals, no allocation) ----------------
__device__ float g_qkv [(size_t)MROWS * OPSZ];
__device__ float g_q   [(size_t)BATCH * NH  * SEQ * HD];
__device__ float g_k   [(size_t)BATCH * NKV * SEQ * HD];
__device__ float g_v   [(size_t)BATCH * NKV * SEQ * HD];  // TRANSPOSED: [b,kvh][d][s]
__device__ float g_att [(size_t)MROWS * HID];

// ============================================================
//          TF32 MMA + ldmatrix helpers
// ============================================================
__device__ __forceinline__ uint32_t f2tf32(float x) {
    uint32_t r;
    asm("cvt.rna.tf32.f32 %0, %1;" : "=r"(r) : "f"(x));
    return r;
}

__device__ __forceinline__ void mma_tf32(float* c, const uint32_t* a, const uint32_t* b) {
    asm volatile(
        "mma.sync.aligned.m16n8k8.row.col.f32.tf32.tf32.f32 "
        "{%0,%1,%2,%3}, {%4,%5,%6,%7}, {%8,%9}, {%0,%1,%2,%3};\n"
        : "+f"(c[0]), "+f"(c[1]), "+f"(c[2]), "+f"(c[3])
        : "r"(a[0]), "r"(a[1]), "r"(a[2]), "r"(a[3]),
          "r"(b[0]), "r"(b[1]));
}

__device__ __forceinline__ void ldmx4(uint32_t* r, uint32_t addr) {
    asm volatile("ldmatrix.sync.aligned.m8n8.x4.shared.b16 {%0,%1,%2,%3}, [%4];"
        : "=r"(r[0]), "=r"(r[1]), "=r"(r[2]), "=r"(r[3]) : "r"(addr));
}

// ============================================================
//                TF32 tensor-core GEMM (ldmatrix edition)
//  C[M,N] = A[M,K] @ B[K,N], row-major fp32 in/out.
//  CTA tile 128x128x32, 8 warps (4m x 2n), warp tile 32x64.
//  A smem [m][k] stride 36; B smem TRANSPOSED [n][k] stride 36.
// ============================================================
#define GBM 128
#define GBN 128
#define GBK 32
#define AS_STRIDE 36     // words; 9 x 16B units == 1 mod 8 -> ldmatrix conflict-free

__global__ __launch_bounds__(256) void tf32_gemm_kernel(
    const float* __restrict__ A, const float* __restrict__ B,
    float* __restrict__ C, int M, int N, int K)
{
    __shared__ uint32_t As[GBM * AS_STRIDE];
    __shared__ uint32_t Bt[GBN * AS_STRIDE];

    const int tid  = threadIdx.x;
    const int lane = tid & 31;
    const int wid  = tid >> 5;
    const int g    = lane >> 2;
    const int tg   = lane & 3;
    const int wm   = (wid & 3) * 32;
    const int wn   = (wid >> 2) * 64;

    const int bm = blockIdx.y * GBM;
    const int bn = blockIdx.x * GBN;

    // B loader mapping: thread covers column n = tid&127, k rows kh..kh+15
    const int bln = tid & 127;
    const int bkh = (tid >> 7) * 16;
    const float* Bcol = B + bn + bln;

    // per-lane ldmatrix addresses
    const int r7  = lane & 7;
    const int r8  = (lane >> 3) & 1;
    const int r16 = lane >> 4;
    uint32_t as_base = (uint32_t)__cvta_generic_to_shared(As);
    uint32_t bt_base = (uint32_t)__cvta_generic_to_shared(Bt);
    uint32_t aaddr[2], baddr[4];
    #pragma unroll
    for (int mt = 0; mt < 2; mt++)
        aaddr[mt] = as_base + (((wm + mt * 16 + r8 * 8 + r7) * AS_STRIDE + r16 * 4) << 2);
    #pragma unroll
    for (int ntp = 0; ntp < 4; ntp++)
        baddr[ntp] = bt_base + (((wn + ntp * 16 + r16 * 8 + r7) * AS_STRIDE + r8 * 4) << 2);

    float4 ra[4];
    float  rbs[16];

    // prologue loads (k0 = 0)
    #pragma unroll
    for (int i = 0; i < 4; i++) {
        int f = tid + 256 * i;
        int r = f >> 3;
        int c = (f & 7) * 4;
        ra[i] = *(const float4*)(A + (size_t)(bm + r) * K + c);
    }
    #pragma unroll
    for (int e = 0; e < 16; e++)
        rbs[e] = Bcol[(size_t)(bkh + e) * N];

    float acc[2][8][4];
    #pragma unroll
    for (int mt = 0; mt < 2; mt++)
        #pragma unroll
        for (int nt = 0; nt < 8; nt++)
            #pragma unroll
            for (int e = 0; e < 4; e++) acc[mt][nt][e] = 0.f;

    for (int k0 = 0; k0 < K; k0 += GBK) {
        // stage A (tf32)
        #pragma unroll
        for (int i = 0; i < 4; i++) {
            int f = tid + 256 * i;
            int r = f >> 3;
            int c = (f & 7) * 4;
            uint32_t* p = &As[r * AS_STRIDE + c];
            p[0] = f2tf32(ra[i].x);
            p[1] = f2tf32(ra[i].y);
            p[2] = f2tf32(ra[i].z);
            p[3] = f2tf32(ra[i].w);
        }
        // stage B transposed (tf32), STS.128 along k
        #pragma unroll
        for (int i = 0; i < 4; i++) {
            uint4 v;
            v.x = f2tf32(rbs[i * 4 + 0]);
            v.y = f2tf32(rbs[i * 4 + 1]);
            v.z = f2tf32(rbs[i * 4 + 2]);
            v.w = f2tf32(rbs[i * 4 + 3]);
            *(uint4*)&Bt[bln * AS_STRIDE + bkh + i * 4] = v;
        }
        __syncthreads();

        // prefetch next tile
        if (k0 + GBK < K) {
            int kn = k0 + GBK;
            #pragma unroll
            for (int i = 0; i < 4; i++) {
                int f = tid + 256 * i;
                int r = f >> 3;
                int c = (f & 7) * 4;
                ra[i] = *(const float4*)(A + (size_t)(bm + r) * K + kn + c);
            }
            #pragma unroll
            for (int e = 0; e < 16; e++)
                rbs[e] = Bcol[(size_t)(kn + bkh + e) * N];
        }

        // compute: 4 k-chunks of 8
        #pragma unroll
        for (int kc = 0; kc < 4; kc++) {
            uint32_t af[2][4];
            ldmx4(af[0], aaddr[0] + kc * 32);
            ldmx4(af[1], aaddr[1] + kc * 32);
            #pragma unroll
            for (int ntp = 0; ntp < 4; ntp++) {
                uint32_t bf[4];
                ldmx4(bf, baddr[ntp] + kc * 32);
                mma_tf32(acc[0][2 * ntp],     af[0], bf);
                mma_tf32(acc[0][2 * ntp + 1], af[0], bf + 2);
                mma_tf32(acc[1][2 * ntp],     af[1], bf);
                mma_tf32(acc[1][2 * ntp + 1], af[1], bf + 2);
            }
        }
        __syncthreads();
    }

    // epilogue
    #pragma unroll
    for (int mt = 0; mt < 2; mt++) {
        int r0 = bm + wm + mt * 16 + g;
        #pragma unroll
        for (int nt = 0; nt < 8; nt++) {
            int c0 = bn + wn + nt * 8 + tg * 2;
            float2 lo = make_float2(acc[mt][nt][0], acc[mt][nt][1]);
            float2 hi = make_float2(acc[mt][nt][2], acc[mt][nt][3]);
            *(float2*)(C + (size_t)r0 * N + c0)       = lo;
            *(float2*)(C + (size_t)(r0 + 8) * N + c0) = hi;
        }
    }
}

// ============================ RoPE + split ============================
// V is written TRANSPOSED to global: g_v[b,kvh][d][s]
__global__ __launch_bounds__(256) void rope_split_kernel(
    const float* __restrict__ qkv,
    float* __restrict__ Qb, float* __restrict__ Kb, float* __restrict__ Vb)
{
    const int m = blockIdx.x;
    const int b = m >> 11;
    const int s = m & 2047;
    const int tid = threadIdx.x;

    __shared__ float cosr[48], sinr[48];
    if (tid < 48) {
        float invf = powf(10000.f, -((float)(2 * tid)) / 96.f);
        float ang  = (float)s * invf;
        cosr[tid] = cosf(ang);
        sinr[tid] = sinf(ang);
    }
    __syncthreads();

    const float* row = qkv + (size_t)m * OPSZ;

    for (int idx = tid; idx < (NH + NKV) * 48; idx += 256) {
        int hh = idx / 48;
        int j  = idx % 48;
        float c  = cosr[j];
        float sn = sinr[j];
        if (hh < NH) {
            float x1 = row[hh * HD + j];
            float x2 = row[hh * HD + j + 48];
            size_t base = ((size_t)(b * NH + hh)) * SEQ * HD + (size_t)s * HD;
            Qb[base + j]      = (x1 * c - x2 * sn) * QK_SCALE;
            Qb[base + j + 48] = (x2 * c + x1 * sn) * QK_SCALE;
        } else {
            int kh = hh - NH;
            float x1 = row[NH * HD + kh * HD + j];
            float x2 = row[NH * HD + kh * HD + j + 48];
            size_t base = ((size_t)(b * NKV + kh)) * SEQ * HD + (size_t)s * HD;
            Kb[base + j]      = x1 * c - x2 * sn;
            Kb[base + j + 48] = x2 * c + x1 * sn;
        }
    }
    // V transposed store: Vb[((b*NKV+kh)*HD + d)*SEQ + s]
    for (int idx = tid; idx < NKV * HD; idx += 256) {
        int kh = idx / HD, d = idx % HD;
        Vb[((size_t)(b * NKV + kh) * HD + d) * SEQ + s] =
            row[NH * HD + NKV * HD + idx];
    }
}

// ============================================================
//      Tensor-core flash attention (tf32 MMA + ldmatrix)
//  CTA = (64 q-rows, b*NH+h). 256 threads, 8 warps.
//  QK: warps 4m x 2n -> 16x32.  PV: 16x48.
// ============================================================
#define AT_BQ 64
#define AT_BK 64
#define QK_STRIDE 100   // words; 25 units == 1 mod 8 -> ldmatrix conflict-free
#define VT_STRIDE 68    // words; 17 units == 1 mod 8
#define P_STRIDE  68

#define ATTN_SMEM_U32 (AT_BQ*QK_STRIDE + AT_BK*QK_STRIDE + HD*VT_STRIDE + AT_BQ*P_STRIDE + 3*AT_BQ)
#define ATTN_SMEM_BYTES (ATTN_SMEM_U32 * 4)

__global__ __launch_bounds__(256, 2) void attn_tc_kernel(
    const float* __restrict__ Q, const float* __restrict__ K,
    const float* __restrict__ V, float* __restrict__ O)
{
    extern __shared__ uint32_t smu[];
    uint32_t* q_s = smu;                           // [64][100] tf32
    uint32_t* k_s = q_s + AT_BQ * QK_STRIDE;       // [64][100] tf32 ([n][k] for QK B)
    uint32_t* vt_s = k_s + AT_BK * QK_STRIDE;      // [96][68] tf32 ([d][j] = [n][k] for PV B)
    float*    p_s = (float*)(vt_s + HD * VT_STRIDE); // [64][68]
    float*    m_s = p_s + AT_BQ * P_STRIDE;
    float*    l_s = m_s + AT_BQ;
    float*    al_s = l_s + AT_BQ;

    const int tid  = threadIdx.x;
    const int lane = tid & 31;
    const int wid  = tid >> 5;
    const int g    = lane >> 2;
    const int tg   = lane & 3;
    const int wm   = (wid & 3) * 16;       // warp q-row offset
    const int wn   = (wid >> 2) * 32;      // warp kv-col offset (QK)
    const int wnp  = (wid >> 2) * 48;      // warp d-col offset (PV)

    const int tileq = blockIdx.x;
    const int bh = blockIdx.y;
    const int b  = bh >> 5;
    const int h  = bh & 31;
    const int kvh = h >> 2;
    const int q0 = tileq * AT_BQ;

    const float* Qb = Q + (size_t)bh * SEQ * HD;
    const float* Kb = K + (size_t)(b * NKV + kvh) * SEQ * HD;
    const float* Vb = V + (size_t)(b * NKV + kvh) * HD * SEQ;  // [d][s]

    // per-lane ldmatrix addresses
    const int r7  = lane & 7;
    const int r8  = (lane >> 3) & 1;
    const int r16 = lane >> 4;
    uint32_t q_base = (uint32_t)__cvta_generic_to_shared(q_s);
    uint32_t k_base = (uint32_t)__cvta_generic_to_shared(k_s);
    uint32_t v_base = (uint32_t)__cvta_generic_to_shared(vt_s);
    uint32_t p_base = (uint32_t)__cvta_generic_to_shared(p_s);

    uint32_t qaddr = q_base + (((wm + r8 * 8 + r7) * QK_STRIDE + r16 * 4) << 2);
    uint32_t paddr = p_base + (((wm + r8 * 8 + r7) * P_STRIDE + r16 * 4) << 2);
    uint32_t kaddr[2], vaddr[3];
    #pragma unroll
    for (int ntp = 0; ntp < 2; ntp++)
        kaddr[ntp] = k_base + (((wn + ntp * 16 + r16 * 8 + r7) * QK_STRIDE + r8 * 4) << 2);
    #pragma unroll
    for (int ntp = 0; ntp < 3; ntp++)
        vaddr[ntp] = v_base + (((wnp + ntp * 16 + r16 * 8 + r7) * VT_STRIDE + r8 * 4) << 2);

    // ---- load Q tile (pre-scaled), rounded to tf32 ----
    for (int f = tid; f < AT_BQ * 24; f += 256) {
        int row = f / 24;
        int cg  = (f % 24) * 4;
        float4 v = *(const float4*)(Qb + (size_t)(q0 + row) * HD + cg);
        uint32_t* p = &q_s[row * QK_STRIDE + cg];
        p[0] = f2tf32(v.x); p[1] = f2tf32(v.y);
        p[2] = f2tf32(v.z); p[3] = f2tf32(v.w);
    }
    if (tid < AT_BQ) { m_s[tid] = -1e30f; l_s[tid] = 0.f; }

    float acc[6][4];
    #pragma unroll
    for (int nt = 0; nt < 6; nt++)
        #pragma unroll
        for (int e = 0; e < 4; e++) acc[nt][e] = 0.f;

    const int ntiles = tileq + 1;
    for (int t = 0; t < ntiles; t++) {
        const int k0 = t * AT_BK;
        __syncthreads();

        // ---- load K tile [j][d] (tf32) ----
        for (int f = tid; f < AT_BK * 24; f += 256) {
            int row = f / 24;
            int cg  = (f % 24) * 4;
            float4 kv4 = *(const float4*)(Kb + (size_t)(k0 + row) * HD + cg);
            uint32_t* p = &k_s[row * QK_STRIDE + cg];
            p[0] = f2tf32(kv4.x); p[1] = f2tf32(kv4.y);
            p[2] = f2tf32(kv4.z); p[3] = f2tf32(kv4.w);
        }
        // ---- load V tile [d][j] (tf32), global already transposed ----
        #pragma unroll
        for (int i = 0; i < 6; i++) {
            int f = tid + 256 * i;            // f < 1536
            int d = f >> 4;
            int j4 = (f & 15) * 4;
            float4 vv4 = *(const float4*)(Vb + (size_t)d * SEQ + k0 + j4);
            uint4 w;
            w.x = f2tf32(vv4.x); w.y = f2tf32(vv4.y);
            w.z = f2tf32(vv4.z); w.w = f2tf32(vv4.w);
            *(uint4*)&vt_s[d * VT_STRIDE + j4] = w;
        }
        __syncthreads();

        // ---- S = Q K^T via MMA: K=96 ----
        float s4[4][4];
        #pragma unroll
        for (int nt = 0; nt < 4; nt++)
            #pragma unroll
            for (int e = 0; e < 4; e++) s4[nt][e] = 0.f;

        #pragma unroll
        for (int kc = 0; kc < 12; kc++) {
            uint32_t a[4];
            ldmx4(a, qaddr + kc * 32);
            #pragma unroll
            for (int ntp = 0; ntp < 2; ntp++) {
                uint32_t bf[4];
                ldmx4(bf, kaddr[ntp] + kc * 32);
                mma_tf32(s4[2 * ntp],     a, bf);
                mma_tf32(s4[2 * ntp + 1], a, bf + 2);
            }
        }

        // ---- mask (diag tile) + store scores ----
        const bool diag = (t == tileq);
        const int row0 = q0 + wm + g;
        #pragma unroll
        for (int nt = 0; nt < 4; nt++) {
            int col = k0 + wn + nt * 8 + 2 * tg;
            float v0 = s4[nt][0], v1 = s4[nt][1];
            float v2 = s4[nt][2], v3 = s4[nt][3];
            if (diag) {
                if (col     > row0)     v0 = -1e30f;
                if (col + 1 > row0)     v1 = -1e30f;
                if (col     > row0 + 8) v2 = -1e30f;
                if (col + 1 > row0 + 8) v3 = -1e30f;
            }
            int c = wn + nt * 8 + 2 * tg;
            *(float2*)&p_s[(wm + g) * P_STRIDE + c]     = make_float2(v0, v1);
            *(float2*)&p_s[(wm + g + 8) * P_STRIDE + c] = make_float2(v2, v3);
        }
        __syncthreads();

        // ---- online softmax: 4 threads per row ----
        {
            const int r  = tid >> 2;
            const int qt = tid & 3;
            float* prow = &p_s[r * P_STRIDE + qt * 16];
            float mold = m_s[r];
            float mt = mold;
            #pragma unroll
            for (int j = 0; j < 16; j++) mt = fmaxf(mt, prow[j]);
            mt = fmaxf(mt, __shfl_xor_sync(0xffffffffu, mt, 1));
            mt = fmaxf(mt, __shfl_xor_sync(0xffffffffu, mt, 2));
            float alpha = __expf(mold - mt);
            float sum = 0.f;
            #pragma unroll
            for (int j = 0; j < 16; j++) {
                float e = __expf(prow[j] - mt);
                sum += e;
                prow[j] = __uint_as_float(f2tf32(e));  // pre-round for MMA
            }
            sum += __shfl_xor_sync(0xffffffffu, sum, 1);
            sum += __shfl_xor_sync(0xffffffffu, sum, 2);
            if (qt == 0) {
                m_s[r]  = mt;
                l_s[r]  = l_s[r] * alpha + sum;
                al_s[r] = alpha;
            }
        }
        __syncthreads();

        // ---- rescale O accumulators ----
        {
            float a0 = al_s[wm + g];
            float a1 = al_s[wm + g + 8];
            #pragma unroll
            for (int nt = 0; nt < 6; nt++) {
                acc[nt][0] *= a0; acc[nt][1] *= a0;
                acc[nt][2] *= a1; acc[nt][3] *= a1;
            }
        }

        // ---- O += P V via MMA: K=64 ----
        #pragma unroll
        for (int kc = 0; kc < 8; kc++) {
            uint32_t a[4];
            ldmx4(a, paddr + kc * 32);
            #pragma unroll
            for (int ntp = 0; ntp < 3; ntp++) {
                uint32_t bf[4];
                ldmx4(bf, vaddr[ntp] + kc * 32);
                mma_tf32(acc[2 * ntp],     a, bf);
                mma_tf32(acc[2 * ntp + 1], a, bf + 2);
            }
        }
    }

    // ---- epilogue: normalize and write O ----
    {
        const int r0 = wm + g;
        const float inv0 = 1.f / l_s[r0];
        const float inv1 = 1.f / l_s[r0 + 8];
        size_t base0 = ((size_t)(b * SEQ + q0 + r0)) * HID + h * HD;
        size_t base1 = base0 + 8 * HID;
        #pragma unroll
        for (int nt = 0; nt < 6; nt++) {
            int c = wnp + nt * 8 + 2 * tg;
            *(float2*)(O + base0 + c) = make_float2(acc[nt][0] * inv0, acc[nt][1] * inv0);
            *(float2*)(O + base1 + c) = make_float2(acc[nt][2] * inv1, acc[nt][3] * inv1);
        }
    }
}

// ============================ launch ============================
extern "C" void kernel_launch(void* const* d_in, const int* in_sizes, int n_in,
                              void* d_out, int out_size)
{
    const float* hs   = (const float*)d_in[0];   // hidden_states
    // d_in[1] = position_ids (arange, unused)
    // d_in[2] = attention_mask (causal, unused)
    const float* Wqkv = (const float*)d_in[3];
    const float* Wo   = (const float*)d_in[4];
    float* out = (float*)d_out;

    float *qkv, *Qb, *Kb, *Vb, *att;
    cudaGetSymbolAddress((void**)&qkv, g_qkv);
    cudaGetSymbolAddress((void**)&Qb,  g_q);
    cudaGetSymbolAddress((void**)&Kb,  g_k);
    cudaGetSymbolAddress((void**)&Vb,  g_v);
    cudaGetSymbolAddress((void**)&att, g_att);

    cudaFuncSetAttribute(attn_tc_kernel,
                         cudaFuncAttributeMaxDynamicSharedMemorySize,
                         ATTN_SMEM_BYTES);

    // 1) QKV projection (tf32 tensor cores + ldmatrix)
    tf32_gemm_kernel<<<dim3(OPSZ / GBN, MROWS / GBM), 256>>>(hs, Wqkv, qkv,
                                                             MROWS, OPSZ, HID);
    // 2) RoPE + split (V transposed to [d][s])
    rope_split_kernel<<<MROWS, 256>>>(qkv, Qb, Kb, Vb);

    // 3) causal GQA flash attention (tf32 + ldmatrix)
    attn_tc_kernel<<<dim3(SEQ / AT_BQ, BATCH * NH), 256, ATTN_SMEM_BYTES>>>(
        Qb, Kb, Vb, att);

    // 4) output projection (tf32 tensor cores + ldmatrix)
    tf32_gemm_kernel<<<dim3(HID / GBN, MROWS / GBM), 256>>>(att, Wo, out,
                                                            MROWS, HID, HID);
}

// round 5
// speedup vs baseline: 4.4306x; 1.2045x over previous
#include <cuda_runtime.h>
#include <cuda_bf16.h>
#include <math.h>
#include <stdint.h>

// Problem constants
#define BATCH   2
#define SEQ     2048
#define HID     3072
#define NH      32
#define NKV     8
#define HD      96
#define OPSZ    4608          // NH*HD + 2*NKV*HD
#define MROWS   4096          // BATCH*SEQ
#define QK_SCALE 0.10206207261596577f  // 1/sqrt(96)

// ---------------- scratch (device globals, no allocation) ----------------
__device__ float g_qkv  [(size_t)MROWS * OPSZ];
__device__ float g_q    [(size_t)BATCH * NH  * SEQ * HD];
__device__ float g_k    [(size_t)BATCH * NKV * SEQ * HD];
__device__ float g_v    [(size_t)BATCH * NKV * SEQ * HD];  // TRANSPOSED: [b,kvh][d][s]
__device__ float g_att  [(size_t)MROWS * HID];
__device__ float g_hs_r [(size_t)MROWS * HID];             // tf32-rounded hidden_states
__device__ float g_wqkvt[(size_t)OPSZ * HID];              // Wqkv^T [n][k], tf32-rounded
__device__ float g_wot  [(size_t)HID * HID];               // Wo^T   [n][k], tf32-rounded

// ============================================================
//          TF32 MMA + ldmatrix + cp.async helpers
// ============================================================
__device__ __forceinline__ uint32_t f2tf32(float x) {
    uint32_t r;
    asm("cvt.rna.tf32.f32 %0, %1;" : "=r"(r) : "f"(x));
    return r;
}
__device__ __forceinline__ float f2tf32f(float x) {
    return __uint_as_float(f2tf32(x));
}

__device__ __forceinline__ void mma_tf32(float* c, const uint32_t* a, const uint32_t* b) {
    asm volatile(
        "mma.sync.aligned.m16n8k8.row.col.f32.tf32.tf32.f32 "
        "{%0,%1,%2,%3}, {%4,%5,%6,%7}, {%8,%9}, {%0,%1,%2,%3};\n"
        : "+f"(c[0]), "+f"(c[1]), "+f"(c[2]), "+f"(c[3])
        : "r"(a[0]), "r"(a[1]), "r"(a[2]), "r"(a[3]),
          "r"(b[0]), "r"(b[1]));
}

__device__ __forceinline__ void ldmx4(uint32_t* r, uint32_t addr) {
    asm volatile("ldmatrix.sync.aligned.m8n8.x4.shared.b16 {%0,%1,%2,%3}, [%4];"
        : "=r"(r[0]), "=r"(r[1]), "=r"(r[2]), "=r"(r[3]) : "r"(addr));
}

__device__ __forceinline__ void cp16(uint32_t dst, const void* src) {
    asm volatile("cp.async.cg.shared.global [%0], [%1], 16;" :: "r"(dst), "l"(src));
}
__device__ __forceinline__ void cp_commit() {
    asm volatile("cp.async.commit_group;");
}
template<int N> __device__ __forceinline__ void cp_wait() {
    asm volatile("cp.async.wait_group %0;" :: "n"(N));
}

// ============================================================
//            pre-pass kernels (tf32 rounding)
// ============================================================
__global__ __launch_bounds__(256) void round_copy_kernel(
    const float* __restrict__ src, float* __restrict__ dst)
{
    int i = blockIdx.x * 256 + threadIdx.x;
    float4 v = ((const float4*)src)[i];
    v.x = f2tf32f(v.x); v.y = f2tf32f(v.y);
    v.z = f2tf32f(v.z); v.w = f2tf32f(v.w);
    ((float4*)dst)[i] = v;
}

// dst[N][K] = round(src[K][N]); tiled transpose
__global__ __launch_bounds__(256) void transpose_round_kernel(
    const float* __restrict__ src, float* __restrict__ dst, int K, int N)
{
    __shared__ float tile[32][33];
    const int n0 = blockIdx.x * 32;
    const int k0 = blockIdx.y * 32;
    const int tx = threadIdx.x & 31;
    const int ty = threadIdx.x >> 5;      // 0..7
    #pragma unroll
    for (int i = 0; i < 4; i++)
        tile[ty + 8 * i][tx] = src[(size_t)(k0 + ty + 8 * i) * N + n0 + tx];
    __syncthreads();
    #pragma unroll
    for (int i = 0; i < 4; i++)
        dst[(size_t)(n0 + ty + 8 * i) * K + k0 + tx] = f2tf32f(tile[tx][ty + 8 * i]);
}

// ============================================================
//    TF32 GEMM, 3-stage cp.async pipeline + ldmatrix
//  C[M,N] = A[M,K] @ Bt[N,K]^T. Inputs pre-rounded to tf32.
//  CTA 128x128x32, 8 warps (4m x 2n), warp tile 32x64.
// ============================================================
#define GBM 128
#define GBN 128
#define GBK 32
#define AS_STRIDE 36            // words; 144B rows -> ldmatrix conflict-free
#define A_TILE_WORDS (GBM * AS_STRIDE)      // 4608
#define STAGE_WORDS  (2 * A_TILE_WORDS)     // 9216
#define NSTAGE 3
#define GEMM_SMEM_BYTES (NSTAGE * STAGE_WORDS * 4)   // 110592

__global__ __launch_bounds__(256, 2) void tf32_gemm_kernel(
    const float* __restrict__ A, const float* __restrict__ Bt,
    float* __restrict__ C, int M, int N, int K)
{
    extern __shared__ uint32_t smg[];

    const int tid  = threadIdx.x;
    const int lane = tid & 31;
    const int wid  = tid >> 5;
    const int g    = lane >> 2;
    const int tg   = lane & 3;
    const int wm   = (wid & 3) * 32;
    const int wn   = (wid >> 2) * 64;

    const int bm = blockIdx.y * GBM;
    const int bn = blockIdx.x * GBN;

    // loader mapping: thread covers rows r0+32i, fixed 4-word col group
    const int r0 = tid >> 3;            // 0..31
    const int cg = (tid & 7) * 4;       // 0..28
    const float* Ap[4];
    const float* Bp[4];
    #pragma unroll
    for (int i = 0; i < 4; i++) {
        Ap[i] = A  + (size_t)(bm + r0 + 32 * i) * K + cg;
        Bp[i] = Bt + (size_t)(bn + r0 + 32 * i) * K + cg;
    }
    const uint32_t sm_base = (uint32_t)__cvta_generic_to_shared(smg);
    const uint32_t adst = sm_base + ((r0 * AS_STRIDE + cg) << 2);
    const uint32_t bdst = adst + (A_TILE_WORDS << 2);

    // per-lane ldmatrix addresses (within stage 0)
    const int r7  = lane & 7;
    const int r8  = (lane >> 3) & 1;
    const int r16 = lane >> 4;
    uint32_t aaddr[2], baddr[4];
    #pragma unroll
    for (int mt = 0; mt < 2; mt++)
        aaddr[mt] = sm_base + (((wm + mt * 16 + r8 * 8 + r7) * AS_STRIDE + r16 * 4) << 2);
    #pragma unroll
    for (int ntp = 0; ntp < 4; ntp++)
        baddr[ntp] = sm_base + ((A_TILE_WORDS + (wn + ntp * 16 + r16 * 8 + r7) * AS_STRIDE + r8 * 4) << 2);

    const int nk = K / GBK;

    // prologue: stages 0,1
    #pragma unroll
    for (int s = 0; s < 2; s++) {
        uint32_t so = s * (STAGE_WORDS << 2);
        #pragma unroll
        for (int i = 0; i < 4; i++) {
            cp16(adst + so + i * ((32 * AS_STRIDE) << 2), Ap[i] + s * GBK);
            cp16(bdst + so + i * ((32 * AS_STRIDE) << 2), Bp[i] + s * GBK);
        }
        cp_commit();
    }

    float acc[2][8][4];
    #pragma unroll
    for (int mt = 0; mt < 2; mt++)
        #pragma unroll
        for (int nt = 0; nt < 8; nt++)
            #pragma unroll
            for (int e = 0; e < 4; e++) acc[mt][nt][e] = 0.f;

    for (int kt = 0; kt < nk; kt++) {
        cp_wait<1>();
        __syncthreads();

        // issue stage kt+2 (buffer free: computed at iter kt-1)
        if (kt + 2 < nk) {
            uint32_t so = ((kt + 2) % NSTAGE) * (STAGE_WORDS << 2);
            int ko = (kt + 2) * GBK;
            #pragma unroll
            for (int i = 0; i < 4; i++) {
                cp16(adst + so + i * ((32 * AS_STRIDE) << 2), Ap[i] + ko);
                cp16(bdst + so + i * ((32 * AS_STRIDE) << 2), Bp[i] + ko);
            }
        }
        cp_commit();

        // compute stage kt
        const uint32_t so = (kt % NSTAGE) * (STAGE_WORDS << 2);
        #pragma unroll
        for (int kc = 0; kc < 4; kc++) {
            uint32_t af[2][4];
            ldmx4(af[0], aaddr[0] + so + kc * 32);
            ldmx4(af[1], aaddr[1] + so + kc * 32);
            #pragma unroll
            for (int ntp = 0; ntp < 4; ntp++) {
                uint32_t bf[4];
                ldmx4(bf, baddr[ntp] + so + kc * 32);
                mma_tf32(acc[0][2 * ntp],     af[0], bf);
                mma_tf32(acc[0][2 * ntp + 1], af[0], bf + 2);
                mma_tf32(acc[1][2 * ntp],     af[1], bf);
                mma_tf32(acc[1][2 * ntp + 1], af[1], bf + 2);
            }
        }
    }

    // epilogue
    #pragma unroll
    for (int mt = 0; mt < 2; mt++) {
        int r = bm + wm + mt * 16 + g;
        #pragma unroll
        for (int nt = 0; nt < 8; nt++) {
            int c0 = bn + wn + nt * 8 + tg * 2;
            *(float2*)(C + (size_t)r * N + c0)       = make_float2(acc[mt][nt][0], acc[mt][nt][1]);
            *(float2*)(C + (size_t)(r + 8) * N + c0) = make_float2(acc[mt][nt][2], acc[mt][nt][3]);
        }
    }
}

// ============================ RoPE + split ============================
// Q/K/V outputs rounded to tf32. V stored TRANSPOSED: g_v[b,kvh][d][s]
__global__ __launch_bounds__(256) void rope_split_kernel(
    const float* __restrict__ qkv,
    float* __restrict__ Qb, float* __restrict__ Kb, float* __restrict__ Vb)
{
    const int m = blockIdx.x;
    const int b = m >> 11;
    const int s = m & 2047;
    const int tid = threadIdx.x;

    __shared__ float cosr[48], sinr[48];
    if (tid < 48) {
        float invf = powf(10000.f, -((float)(2 * tid)) / 96.f);
        float ang  = (float)s * invf;
        cosr[tid] = cosf(ang);
        sinr[tid] = sinf(ang);
    }
    __syncthreads();

    const float* row = qkv + (size_t)m * OPSZ;

    for (int idx = tid; idx < (NH + NKV) * 48; idx += 256) {
        int hh = idx / 48;
        int j  = idx % 48;
        float c  = cosr[j];
        float sn = sinr[j];
        if (hh < NH) {
            float x1 = row[hh * HD + j];
            float x2 = row[hh * HD + j + 48];
            size_t base = ((size_t)(b * NH + hh)) * SEQ * HD + (size_t)s * HD;
            Qb[base + j]      = f2tf32f((x1 * c - x2 * sn) * QK_SCALE);
            Qb[base + j + 48] = f2tf32f((x2 * c + x1 * sn) * QK_SCALE);
        } else {
            int kh = hh - NH;
            float x1 = row[NH * HD + kh * HD + j];
            float x2 = row[NH * HD + kh * HD + j + 48];
            size_t base = ((size_t)(b * NKV + kh)) * SEQ * HD + (size_t)s * HD;
            Kb[base + j]      = f2tf32f(x1 * c - x2 * sn);
            Kb[base + j + 48] = f2tf32f(x2 * c + x1 * sn);
        }
    }
    for (int idx = tid; idx < NKV * HD; idx += 256) {
        int kh = idx / HD, d = idx % HD;
        Vb[((size_t)(b * NKV + kh) * HD + d) * SEQ + s] =
            f2tf32f(row[NH * HD + NKV * HD + idx]);
    }
}

// ============================================================
//   Tensor-core flash attention (tf32 + ldmatrix + cp.async)
//  CTA = (64 q-rows, b*NH+h). 256 threads, 8 warps.
//  Globals pre-rounded to tf32 -> cp.async staging is exact.
// ============================================================
#define AT_BQ 64
#define AT_BK 64
#define QK_STRIDE 100   // words; conflict-free ldmatrix
#define VT_STRIDE 68
#define P_STRIDE  68

#define ATTN_SMEM_U32 (AT_BQ*QK_STRIDE + AT_BK*QK_STRIDE + HD*VT_STRIDE + AT_BQ*P_STRIDE + 3*AT_BQ)
#define ATTN_SMEM_BYTES (ATTN_SMEM_U32 * 4)

__global__ __launch_bounds__(256, 2) void attn_tc_kernel(
    const float* __restrict__ Q, const float* __restrict__ K,
    const float* __restrict__ V, float* __restrict__ O)
{
    extern __shared__ uint32_t smu[];
    uint32_t* q_s = smu;                              // [64][100]
    uint32_t* k_s = q_s + AT_BQ * QK_STRIDE;          // [64][100] ([n][k] for QK B)
    uint32_t* vt_s = k_s + AT_BK * QK_STRIDE;         // [96][68]  ([n][k] for PV B)
    float*    p_s = (float*)(vt_s + HD * VT_STRIDE);  // [64][68]
    float*    m_s = p_s + AT_BQ * P_STRIDE;
    float*    l_s = m_s + AT_BQ;
    float*    al_s = l_s + AT_BQ;

    const int tid  = threadIdx.x;
    const int lane = tid & 31;
    const int wid  = tid >> 5;
    const int g    = lane >> 2;
    const int tg   = lane & 3;
    const int wm   = (wid & 3) * 16;
    const int wn   = (wid >> 2) * 32;
    const int wnp  = (wid >> 2) * 48;

    const int tileq = blockIdx.x;
    const int bh = blockIdx.y;
    const int b  = bh >> 5;
    const int h  = bh & 31;
    const int kvh = h >> 2;
    const int q0 = tileq * AT_BQ;

    const float* Qb = Q + (size_t)bh * SEQ * HD;
    const float* Kb = K + (size_t)(b * NKV + kvh) * SEQ * HD;
    const float* Vb = V + (size_t)(b * NKV + kvh) * HD * SEQ;  // [d][s]

    const uint32_t q_base = (uint32_t)__cvta_generic_to_shared(q_s);
    const uint32_t k_base = (uint32_t)__cvta_generic_to_shared(k_s);
    const uint32_t v_base = (uint32_t)__cvta_generic_to_shared(vt_s);
    const uint32_t p_base = (uint32_t)__cvta_generic_to_shared(p_s);

    // cp.async loader mappings (6 x 16B per thread per tile)
    const int qk_row = tid / 24 ;       // not used directly; recompute per i
    (void)qk_row;

    // per-lane ldmatrix addresses
    const int r7  = lane & 7;
    const int r8  = (lane >> 3) & 1;
    const int r16 = lane >> 4;
    uint32_t qaddr = q_base + (((wm + r8 * 8 + r7) * QK_STRIDE + r16 * 4) << 2);
    uint32_t paddr = p_base + (((wm + r8 * 8 + r7) * P_STRIDE + r16 * 4) << 2);
    uint32_t kaddr[2], vaddr[3];
    #pragma unroll
    for (int ntp = 0; ntp < 2; ntp++)
        kaddr[ntp] = k_base + (((wn + ntp * 16 + r16 * 8 + r7) * QK_STRIDE + r8 * 4) << 2);
    #pragma unroll
    for (int ntp = 0; ntp < 3; ntp++)
        vaddr[ntp] = v_base + (((wnp + ntp * 16 + r16 * 8 + r7) * VT_STRIDE + r8 * 4) << 2);

    // ---- prologue: cp.async Q tile + K tile 0 ----
    #pragma unroll
    for (int i = 0; i < 6; i++) {
        int f = tid + 256 * i;          // < 1536
        int row = f / 24;
        int c4  = (f % 24) * 4;
        cp16(q_base + ((row * QK_STRIDE + c4) << 2),
             Qb + (size_t)(q0 + row) * HD + c4);
        cp16(k_base + ((row * QK_STRIDE + c4) << 2),
             Kb + (size_t)row * HD + c4);
    }
    cp_commit();

    if (tid < AT_BQ) { m_s[tid] = -1e30f; l_s[tid] = 0.f; }

    float acc[6][4];
    #pragma unroll
    for (int nt = 0; nt < 6; nt++)
        #pragma unroll
        for (int e = 0; e < 4; e++) acc[nt][e] = 0.f;

    const int ntiles = tileq + 1;
    for (int t = 0; t < ntiles; t++) {
        const int k0 = t * AT_BK;
        __syncthreads();       // prev iter fully done (v_s, p_s free)

        // issue V_t  (v_s free now)
        #pragma unroll
        for (int i = 0; i < 6; i++) {
            int f = tid + 256 * i;
            int d = f >> 4;
            int j4 = (f & 15) * 4;
            cp16(v_base + ((d * VT_STRIDE + j4) << 2),
                 Vb + (size_t)d * SEQ + k0 + j4);
        }
        cp_commit();
        cp_wait<0>();          // Q (+K_t from prefetch) + V_t all arrived
        __syncthreads();

        // ---- S = Q K^T via MMA: K=96 ----
        float s4[4][4];
        #pragma unroll
        for (int nt = 0; nt < 4; nt++)
            #pragma unroll
            for (int e = 0; e < 4; e++) s4[nt][e] = 0.f;

        #pragma unroll
        for (int kc = 0; kc < 12; kc++) {
            uint32_t a[4];
            ldmx4(a, qaddr + kc * 32);
            #pragma unroll
            for (int ntp = 0; ntp < 2; ntp++) {
                uint32_t bf[4];
                ldmx4(bf, kaddr[ntp] + kc * 32);
                mma_tf32(s4[2 * ntp],     a, bf);
                mma_tf32(s4[2 * ntp + 1], a, bf + 2);
            }
        }

        // ---- mask (diag tile) + store scores ----
        const bool diag = (t == tileq);
        const int row0 = q0 + wm + g;
        #pragma unroll
        for (int nt = 0; nt < 4; nt++) {
            int col = k0 + wn + nt * 8 + 2 * tg;
            float v0 = s4[nt][0], v1 = s4[nt][1];
            float v2 = s4[nt][2], v3 = s4[nt][3];
            if (diag) {
                if (col     > row0)     v0 = -1e30f;
                if (col + 1 > row0)     v1 = -1e30f;
                if (col     > row0 + 8) v2 = -1e30f;
                if (col + 1 > row0 + 8) v3 = -1e30f;
            }
            int c = wn + nt * 8 + 2 * tg;
            *(float2*)&p_s[(wm + g) * P_STRIDE + c]     = make_float2(v0, v1);
            *(float2*)&p_s[(wm + g + 8) * P_STRIDE + c] = make_float2(v2, v3);
        }
        __syncthreads();       // QK done -> k_s free; p_s visible

        // prefetch K_{t+1} into k_s, overlapped with softmax + PV
        if (t + 1 < ntiles) {
            const int k0n = k0 + AT_BK;
            #pragma unroll
            for (int i = 0; i < 6; i++) {
                int f = tid + 256 * i;
                int row = f / 24;
                int c4  = (f % 24) * 4;
                cp16(k_base + ((row * QK_STRIDE + c4) << 2),
                     Kb + (size_t)(k0n + row) * HD + c4);
            }
        }
        cp_commit();

        // ---- online softmax: 4 threads per row ----
        {
            const int r  = tid >> 2;
            const int qt = tid & 3;
            float* prow = &p_s[r * P_STRIDE + qt * 16];
            float mold = m_s[r];
            float mt = mold;
            #pragma unroll
            for (int j = 0; j < 16; j++) mt = fmaxf(mt, prow[j]);
            mt = fmaxf(mt, __shfl_xor_sync(0xffffffffu, mt, 1));
            mt = fmaxf(mt, __shfl_xor_sync(0xffffffffu, mt, 2));
            float alpha = __expf(mold - mt);
            float sum = 0.f;
            #pragma unroll
            for (int j = 0; j < 16; j++) {
                float e = __expf(prow[j] - mt);
                sum += e;
                prow[j] = __uint_as_float(f2tf32(e));
            }
            sum += __shfl_xor_sync(0xffffffffu, sum, 1);
            sum += __shfl_xor_sync(0xffffffffu, sum, 2);
            if (qt == 0) {
                m_s[r]  = mt;
                l_s[r]  = l_s[r] * alpha + sum;
                al_s[r] = alpha;
            }
        }
        __syncthreads();

        // ---- rescale O accumulators ----
        {
            float a0 = al_s[wm + g];
            float a1 = al_s[wm + g + 8];
            #pragma unroll
            for (int nt = 0; nt < 6; nt++) {
                acc[nt][0] *= a0; acc[nt][1] *= a0;
                acc[nt][2] *= a1; acc[nt][3] *= a1;
            }
        }

        // ---- O += P V via MMA: K=64 ----
        #pragma unroll
        for (int kc = 0; kc < 8; kc++) {
            uint32_t a[4];
            ldmx4(a, paddr + kc * 32);
            #pragma unroll
            for (int ntp = 0; ntp < 3; ntp++) {
                uint32_t bf[4];
                ldmx4(bf, vaddr[ntp] + kc * 32);
                mma_tf32(acc[2 * ntp],     a, bf);
                mma_tf32(acc[2 * ntp + 1], a, bf + 2);
            }
        }
    }

    // ---- epilogue: normalize, round to tf32 (O-proj A operand), write ----
    {
        const int r0 = wm + g;
        const float inv0 = 1.f / l_s[r0];
        const float inv1 = 1.f / l_s[r0 + 8];
        size_t base0 = ((size_t)(b * SEQ + q0 + r0)) * HID + h * HD;
        size_t base1 = base0 + 8 * HID;
        #pragma unroll
        for (int nt = 0; nt < 6; nt++) {
            int c = wnp + nt * 8 + 2 * tg;
            *(float2*)(O + base0 + c) =
                make_float2(f2tf32f(acc[nt][0] * inv0), f2tf32f(acc[nt][1] * inv0));
            *(float2*)(O + base1 + c) =
                make_float2(f2tf32f(acc[nt][2] * inv1), f2tf32f(acc[nt][3] * inv1));
        }
    }
}

// ============================ launch ============================
extern "C" void kernel_launch(void* const* d_in, const int* in_sizes, int n_in,
                              void* d_out, int out_size)
{
    const float* hs   = (const float*)d_in[0];   // hidden_states
    // d_in[1] = position_ids (arange, unused)
    // d_in[2] = attention_mask (causal, unused)
    const float* Wqkv = (const float*)d_in[3];
    const float* Wo   = (const float*)d_in[4];
    float* out = (float*)d_out;

    float *qkv, *Qb, *Kb, *Vb, *att, *hs_r, *wqkvt, *wot;
    cudaGetSymbolAddress((void**)&qkv,   g_qkv);
    cudaGetSymbolAddress((void**)&Qb,    g_q);
    cudaGetSymbolAddress((void**)&Kb,    g_k);
    cudaGetSymbolAddress((void**)&Vb,    g_v);
    cudaGetSymbolAddress((void**)&att,   g_att);
    cudaGetSymbolAddress((void**)&hs_r,  g_hs_r);
    cudaGetSymbolAddress((void**)&wqkvt, g_wqkvt);
    cudaGetSymbolAddress((void**)&wot,   g_wot);

    cudaFuncSetAttribute(tf32_gemm_kernel,
                         cudaFuncAttributeMaxDynamicSharedMemorySize,
                         GEMM_SMEM_BYTES);
    cudaFuncSetAttribute(attn_tc_kernel,
                         cudaFuncAttributeMaxDynamicSharedMemorySize,
                         ATTN_SMEM_BYTES);

    // 0) pre-round hidden_states; pre-round+transpose weights
    round_copy_kernel<<<(MROWS * HID / 4) / 256, 256>>>(hs, hs_r);
    transpose_round_kernel<<<dim3(OPSZ / 32, HID / 32), 256>>>(Wqkv, wqkvt, HID, OPSZ);
    transpose_round_kernel<<<dim3(HID / 32, HID / 32), 256>>>(Wo, wot, HID, HID);

    // 1) QKV projection (cp.async 3-stage pipeline)
    tf32_gemm_kernel<<<dim3(OPSZ / GBN, MROWS / GBM), 256, GEMM_SMEM_BYTES>>>(
        hs_r, wqkvt, qkv, MROWS, OPSZ, HID);

    // 2) RoPE + split (rounded; V transposed to [d][s])
    rope_split_kernel<<<MROWS, 256>>>(qkv, Qb, Kb, Vb);

    // 3) causal GQA flash attention
    attn_tc_kernel<<<dim3(SEQ / AT_BQ, BATCH * NH), 256, ATTN_SMEM_BYTES>>>(
        Qb, Kb, Vb, att);

    // 4) output projection
    tf32_gemm_kernel<<<dim3(HID / GBN, MROWS / GBM), 256, GEMM_SMEM_BYTES>>>(
        att, wot, out, MROWS, HID, HID);
}